// round 7
// baseline (speedup 1.0000x reference)
#include <cuda_runtime.h>
#include <math.h>

// Problem constants
#define BB    16          // batch
#define B2    32          // 2*batch (fwd+bwd)
#define TT    500         // time
#define HH    1024        // hidden
#define GG    2048        // 2*H gate rows
#define NROWS 16000       // B2*TT

// ---------------- scratch (device globals; no allocation) ----------------
__device__ float g_w[(size_t)NROWS * GG];     // 131 MB: normalized-input projections (per layer, reused)
__device__ float g_hs0[(size_t)B2 * TT * HH]; // 65.5 MB: layer-0 hidden sequence
__device__ float g_h[2 * HH * B2];            // double-buffered h, layout [parity][k][b]
__device__ float g_psum[125 * GG];
__device__ float g_psq[125 * GG];
__device__ float g_scale[GG];
__device__ float g_shift[GG];
__device__ unsigned int g_bar;

// ---------------- GEMM: g_w[r][g] = sum_f A(r,f) * W[g][f] ----------------
// A(r,f) gathers the bidirectional concat on the fly.
//   layer 0: A from x (B,T,512):  b2=r/500, t=r%500; b=b2&15; tt = b2<16 ? t : 499-t
//            A = x[(b*500+tt)*512 + f]
//   layer 1: A from hs0 (32,500,1024), feature dim 2048 = concat(h_f, h_b reversed):
//            f<1024 : hs0[(b*500+tt)*1024 + f]
//            f>=1024: hs0[((b+16)*500 + (499-tt))*1024 + (f-1024)]
__global__ __launch_bounds__(256) void gemm_kernel(const float* __restrict__ X,
                                                   const float* __restrict__ Wm,
                                                   int F, int layer)
{
    __shared__ float As[16 * 129];
    __shared__ float Bs[16 * 129];

    const int tid  = threadIdx.x;
    const int row0 = blockIdx.y * 128;
    const int col0 = blockIdx.x * 128;
    const int tx   = tid & 15;       // N micro-tile index (0..15) -> 8 cols each
    const int ty   = tid >> 4;       // M micro-tile index (0..15) -> 8 rows each
    const int lk   = tid & 15;       // k within tile for loading
    const int lm   = tid >> 4;       // row sub-index for loading

    // Hoist per-loaded-row base pointers
    const float* aptrF[8];
    const float* aptrB[8];
    const float* bptr[8];
#pragma unroll
    for (int i = 0; i < 8; i++) {
        int r  = row0 + lm + i * 16;
        int b2 = r / TT;
        int t  = r - b2 * TT;
        int b  = b2 & 15;
        int tt = (b2 < BB) ? t : (TT - 1 - t);
        if (layer == 0) {
            aptrF[i] = X + (size_t)(b * TT + tt) * 512;
            aptrB[i] = X;  // unused
        } else {
            aptrF[i] = g_hs0 + (size_t)(b * TT + tt) * HH;
            aptrB[i] = g_hs0 + (size_t)((b + 16) * TT + (TT - 1 - tt)) * HH;
        }
        bptr[i] = Wm + (size_t)(col0 + lm + i * 16) * F;
    }

    float acc[8][8];
#pragma unroll
    for (int i = 0; i < 8; i++)
#pragma unroll
        for (int j = 0; j < 8; j++) acc[i][j] = 0.f;

    for (int kk = 0; kk < F; kk += 16) {
        // load A tile (128 x 16), stored As[k][m] with pad 129
#pragma unroll
        for (int i = 0; i < 8; i++) {
            int m = lm + i * 16;
            float v;
            if (layer == 0) {
                v = aptrF[i][kk + lk];
            } else {
                int f = kk + lk;
                v = (f < HH) ? aptrF[i][f] : aptrB[i][f - HH];
            }
            As[lk * 129 + m] = v;
        }
        // load B tile (128 x 16), stored Bs[k][n] with pad 129
#pragma unroll
        for (int i = 0; i < 8; i++) {
            int n = lm + i * 16;
            Bs[lk * 129 + n] = bptr[i][kk + lk];
        }
        __syncthreads();

#pragma unroll
        for (int k = 0; k < 16; k++) {
            float a[8], b[8];
#pragma unroll
            for (int i = 0; i < 8; i++) a[i] = As[k * 129 + ty * 8 + i];
#pragma unroll
            for (int j = 0; j < 8; j++) b[j] = Bs[k * 129 + tx * 8 + j];
#pragma unroll
            for (int i = 0; i < 8; i++)
#pragma unroll
                for (int j = 0; j < 8; j++) acc[i][j] = fmaf(a[i], b[j], acc[i][j]);
        }
        __syncthreads();
    }

    // write C
#pragma unroll
    for (int i = 0; i < 8; i++) {
        size_t base = (size_t)(row0 + ty * 8 + i) * GG + col0 + tx * 8;
        float4 v0 = make_float4(acc[i][0], acc[i][1], acc[i][2], acc[i][3]);
        float4 v1 = make_float4(acc[i][4], acc[i][5], acc[i][6], acc[i][7]);
        *(float4*)(g_w + base)     = v0;
        *(float4*)(g_w + base + 4) = v1;
    }
}

// ---------------- batch-norm stats (deterministic two-stage) ----------------
__global__ void stats_partial_kernel()
{
    int col = blockIdx.x * 256 + threadIdx.x;   // grid.x = 8
    int r0  = blockIdx.y * 128;                 // grid.y = 125
    float s = 0.f, q = 0.f;
    for (int i = 0; i < 128; i++) {
        float v = g_w[(size_t)(r0 + i) * GG + col];
        s += v;
        q += v * v;
    }
    g_psum[blockIdx.y * GG + col] = s;
    g_psq [blockIdx.y * GG + col] = q;
}

__global__ void stats_final_kernel(const float* __restrict__ gamma,
                                   const float* __restrict__ beta)
{
    int col = blockIdx.x * 256 + threadIdx.x;   // grid.x = 8
    float s = 0.f, q = 0.f;
    for (int i = 0; i < 125; i++) {
        s += g_psum[i * GG + col];
        q += g_psq [i * GG + col];
    }
    float mean = s * (1.f / 16000.f);
    float var  = q * (1.f / 16000.f) - mean * mean;
    float sc   = gamma[col] * rsqrtf(var + 1e-5f);
    g_scale[col] = sc;
    g_shift[col] = beta[col] - mean * sc;
}

__global__ void reset_bar_kernel() { g_bar = 0u; }

// ---------------- persistent recurrence ----------------
// grid = 128 blocks (1 per SM, co-resident), 256 threads (8 warps).
// Block j owns h-columns [j*8, j*8+8). Warp w owns column ga = j*8+w,
// i.e. gate rows ga (a-gate) and 1024+ga (z-gate). Lane = batch (32).
// U slice (16 rows x 1024) cached in SMEM for all 500 steps.
// h double-buffered in g_h with layout [parity][k][b]; staged to SMEM each step.
#define REC_SMEM ((16 * 1024 + 1024 * 32) * 4)

__device__ __forceinline__ void grid_barrier(unsigned int phase)
{
    __syncthreads();
    if (threadIdx.x == 0) {
        __threadfence();
        atomicAdd(&g_bar, 1u);
        unsigned int target = phase * gridDim.x;
        while (*((volatile unsigned int*)&g_bar) < target) { }
        __threadfence();
    }
    __syncthreads();
}

__global__ __launch_bounds__(256, 1) void recur_kernel(const float* __restrict__ U,
                                                       float* __restrict__ out,
                                                       int layer)
{
    extern __shared__ float sm[];
    float* Us = sm;                 // 16 * 1024
    float* Hs = sm + 16 * 1024;     // 1024 * 32  ([k][b])

    const int tid  = threadIdx.x;
    const int blk  = blockIdx.x;
    const int w    = tid >> 5;
    const int lane = tid & 31;

    const int ga = blk * 8 + w;      // h-column / a-gate row (0..1023)
    const int gz = HH + ga;          // z-gate row

    // load U slice into SMEM: rows 0..7 = a-rows, 8..15 = z-rows (float4 chunks)
    for (int e = tid; e < 16 * 256; e += 256) {
        int rr = e >> 8;       // 0..15
        int c4 = e & 255;      // float4 index within row
        int grow = (rr < 8) ? (blk * 8 + rr) : (HH + blk * 8 + (rr - 8));
        float4 v = ((const float4*)U)[(size_t)grow * 256 + c4];
        ((float4*)Us)[rr * 256 + c4] = v;
    }

    const float sa  = g_scale[ga], sha = g_shift[ga];
    const float sz  = g_scale[gz], shz = g_shift[gz];

    // zero h parity 0 (128 blocks * 256 threads = 32768 = HH*B2 exactly)
    g_h[blk * 256 + tid] = 0.f;

    grid_barrier(1);

    const float* Ua = Us + w * 1024;
    const float* Uz = Us + (8 + w) * 1024;

    for (int t = 0; t < TT; t++) {
        const int cur = t & 1;
        const int nxt = cur ^ 1;

        // stage current h into SMEM (coalesced float4 copy of 128 KB)
        {
            const float4* hsrc = (const float4*)(g_h + cur * (HH * B2));
            float4* hdst = (float4*)Hs;
            for (int e = tid; e < (HH * B2) / 4; e += 256) hdst[e] = hsrc[e];
        }
        __syncthreads();

        // normalized w contributions (scattered 4B loads, issued early)
        size_t wrow = (size_t)(lane * TT + t) * GG;
        float acc_a = fmaf(g_w[wrow + ga], sa, sha);
        float acc_z = fmaf(g_w[wrow + gz], sz, shz);

#pragma unroll 4
        for (int k = 0; k < HH; k += 4) {
            float4 ua = *(const float4*)(Ua + k);
            float4 uz = *(const float4*)(Uz + k);
            float h0 = Hs[(k + 0) * 32 + lane];
            float h1 = Hs[(k + 1) * 32 + lane];
            float h2 = Hs[(k + 2) * 32 + lane];
            float h3 = Hs[(k + 3) * 32 + lane];
            acc_a = fmaf(ua.x, h0, acc_a);
            acc_a = fmaf(ua.y, h1, acc_a);
            acc_a = fmaf(ua.z, h2, acc_a);
            acc_a = fmaf(ua.w, h3, acc_a);
            acc_z = fmaf(uz.x, h0, acc_z);
            acc_z = fmaf(uz.y, h1, acc_z);
            acc_z = fmaf(uz.z, h2, acc_z);
            acc_z = fmaf(uz.w, h3, acc_z);
        }

        float z    = 1.f / (1.f + expf(-acc_z));
        float hold = Hs[ga * 32 + lane];
        float hn   = z * hold + (1.f - z) * fmaxf(acc_a, 0.f);

        g_h[nxt * (HH * B2) + ga * 32 + lane] = hn;

        if (layer == 0) {
            g_hs0[(size_t)(lane * TT + t) * HH + ga] = hn;
        } else {
            if (lane < BB)
                out[(size_t)(lane * TT + t) * GG + ga] = hn;
            else
                out[(size_t)((lane - BB) * TT + (TT - 1 - t)) * GG + HH + ga] = hn;
        }

        grid_barrier((unsigned int)t + 2u);
    }
}

// ---------------- launch ----------------
extern "C" void kernel_launch(void* const* d_in, const int* in_sizes, int n_in,
                              void* d_out, int out_size)
{
    const float* x  = (const float*)d_in[0];
    const float* w0 = (const float*)d_in[1];
    const float* u0 = (const float*)d_in[2];
    const float* g0 = (const float*)d_in[3];
    const float* b0 = (const float*)d_in[4];
    const float* w1 = (const float*)d_in[5];
    const float* u1 = (const float*)d_in[6];
    const float* g1 = (const float*)d_in[7];
    const float* b1 = (const float*)d_in[8];
    float* out = (float*)d_out;

    cudaFuncSetAttribute(recur_kernel, cudaFuncAttributeMaxDynamicSharedMemorySize, REC_SMEM);

    dim3 ggrid(GG / 128, NROWS / 128);   // (16, 125)
    dim3 sgrid(GG / 256, 125);           // (8, 125)

    // ---- layer 0 ----
    gemm_kernel<<<ggrid, 256>>>(x, w0, 512, 0);
    stats_partial_kernel<<<sgrid, 256>>>();
    stats_final_kernel<<<GG / 256, 256>>>(g0, b0);
    reset_bar_kernel<<<1, 1>>>();
    recur_kernel<<<128, 256, REC_SMEM>>>(u0, out, 0);

    // ---- layer 1 ----
    gemm_kernel<<<ggrid, 256>>>(x, w1, 2048, 1);
    stats_partial_kernel<<<sgrid, 256>>>();
    stats_final_kernel<<<GG / 256, 256>>>(g1, b1);
    reset_bar_kernel<<<1, 1>>>();
    recur_kernel<<<128, 256, REC_SMEM>>>(u1, out, 1);
}

// round 8
// speedup vs baseline: 1.4003x; 1.4003x over previous
#include <cuda_runtime.h>
#include <math.h>

// Problem constants
#define BB    16          // batch
#define B2    32          // 2*batch (fwd+bwd)
#define TT    500         // time
#define HH    1024        // hidden
#define GG    2048        // 2*H gate rows
#define NROWS 16000       // B2*TT
#define HS    (HH * B2)   // 32768 h-state floats

// ---------------- scratch (device globals; no allocation) ----------------
__device__ __align__(128) float g_w  [(size_t)NROWS * GG];   // 131 MB: raw input projections [r][g]
__device__ __align__(128) float g_wT [(size_t)TT * GG * B2]; // 131 MB: normalized, [t][g][b2]
__device__ __align__(128) float g_hs0[(size_t)B2 * TT * HH]; // 65.5 MB: layer-0 hidden sequence
__device__ __align__(128) float g_h  [2 * HS];               // double-buffered h, [parity][k][b]
__device__ __align__(128) float g_psum[125 * GG];
__device__ __align__(128) float g_psq [125 * GG];
__device__ float g_scale[GG];
__device__ float g_shift[GG];
__device__ unsigned int g_bar;

// ---------------- GEMM: g_w[r][g] = sum_f A(r,f) * W[g][f] ----------------
// Double-buffered smem, register prefetch, one __syncthreads per k-tile.
// A(r,f) gathers the bidirectional concat on the fly (see round-6 comments).
__global__ __launch_bounds__(256, 2) void gemm_kernel(const float* __restrict__ X,
                                                      const float* __restrict__ Wm,
                                                      int F, int layer)
{
    __shared__ float As[2][16 * 129];
    __shared__ float Bs[2][16 * 129];

    const int tid  = threadIdx.x;
    const int row0 = blockIdx.y * 128;
    const int col0 = blockIdx.x * 128;
    const int qid  = tid & 3;     // float4 index within a 16-k row segment
    const int lrow = tid >> 2;    // 0..63 ; covers 128 rows in 2 passes

    // Per-thread row base pointers (2 rows per thread)
    const float* aF[2];
    const float* aB[2];
    const float* bp[2];
#pragma unroll
    for (int i = 0; i < 2; i++) {
        int r  = row0 + lrow + i * 64;
        int b2 = r / TT;
        int t  = r - b2 * TT;
        int b  = b2 & 15;
        int tt = (b2 < BB) ? t : (TT - 1 - t);
        if (layer == 0) {
            aF[i] = X + (size_t)(b * TT + tt) * 512;
            aB[i] = aF[i];
        } else {
            aF[i] = g_hs0 + (size_t)(b * TT + tt) * HH;
            aB[i] = g_hs0 + (size_t)((b + 16) * TT + (TT - 1 - tt)) * HH - HH; // aB[f] valid for f>=HH
        }
        bp[i] = Wm + (size_t)(col0 + lrow + i * 64) * F;
    }

    const int ty = tid >> 4, tx = tid & 15;
    float acc[8][8];
#pragma unroll
    for (int i = 0; i < 8; i++)
#pragma unroll
        for (int j = 0; j < 8; j++) acc[i][j] = 0.f;

    float4 ra[2], rb[2];

    // ---- prologue: tile 0 ----
    {
        int f = qid * 4;
#pragma unroll
        for (int i = 0; i < 2; i++) {
            ra[i] = (f < HH) ? *(const float4*)(aF[i] + f) : *(const float4*)(aB[i] + f);
            rb[i] = *(const float4*)(bp[i] + f);
        }
#pragma unroll
        for (int i = 0; i < 2; i++) {
            int m = lrow + i * 64;
            As[0][(qid * 4 + 0) * 129 + m] = ra[i].x;
            As[0][(qid * 4 + 1) * 129 + m] = ra[i].y;
            As[0][(qid * 4 + 2) * 129 + m] = ra[i].z;
            As[0][(qid * 4 + 3) * 129 + m] = ra[i].w;
            Bs[0][(qid * 4 + 0) * 129 + m] = rb[i].x;
            Bs[0][(qid * 4 + 1) * 129 + m] = rb[i].y;
            Bs[0][(qid * 4 + 2) * 129 + m] = rb[i].z;
            Bs[0][(qid * 4 + 3) * 129 + m] = rb[i].w;
        }
    }
    __syncthreads();

    const int nt = F / 16;
    int cur = 0;
    for (int it = 1; it < nt; it++) {
        // prefetch next tile into registers
        int f = it * 16 + qid * 4;
#pragma unroll
        for (int i = 0; i < 2; i++) {
            ra[i] = (f < HH) ? *(const float4*)(aF[i] + f) : *(const float4*)(aB[i] + f);
            rb[i] = *(const float4*)(bp[i] + f);
        }
        // compute current tile (hides gmem latency)
#pragma unroll
        for (int k = 0; k < 16; k++) {
            float a_[8], b_[8];
#pragma unroll
            for (int i2 = 0; i2 < 8; i2++) a_[i2] = As[cur][k * 129 + ty * 8 + i2];
#pragma unroll
            for (int j2 = 0; j2 < 8; j2++) b_[j2] = Bs[cur][k * 129 + tx * 8 + j2];
#pragma unroll
            for (int i2 = 0; i2 < 8; i2++)
#pragma unroll
                for (int j2 = 0; j2 < 8; j2++) acc[i2][j2] = fmaf(a_[i2], b_[j2], acc[i2][j2]);
        }
        // store prefetched tile into the other buffer
        int nb = cur ^ 1;
#pragma unroll
        for (int i = 0; i < 2; i++) {
            int m = lrow + i * 64;
            As[nb][(qid * 4 + 0) * 129 + m] = ra[i].x;
            As[nb][(qid * 4 + 1) * 129 + m] = ra[i].y;
            As[nb][(qid * 4 + 2) * 129 + m] = ra[i].z;
            As[nb][(qid * 4 + 3) * 129 + m] = ra[i].w;
            Bs[nb][(qid * 4 + 0) * 129 + m] = rb[i].x;
            Bs[nb][(qid * 4 + 1) * 129 + m] = rb[i].y;
            Bs[nb][(qid * 4 + 2) * 129 + m] = rb[i].z;
            Bs[nb][(qid * 4 + 3) * 129 + m] = rb[i].w;
        }
        __syncthreads();
        cur = nb;
    }
    // last tile compute
#pragma unroll
    for (int k = 0; k < 16; k++) {
        float a_[8], b_[8];
#pragma unroll
        for (int i2 = 0; i2 < 8; i2++) a_[i2] = As[cur][k * 129 + ty * 8 + i2];
#pragma unroll
        for (int j2 = 0; j2 < 8; j2++) b_[j2] = Bs[cur][k * 129 + tx * 8 + j2];
#pragma unroll
        for (int i2 = 0; i2 < 8; i2++)
#pragma unroll
            for (int j2 = 0; j2 < 8; j2++) acc[i2][j2] = fmaf(a_[i2], b_[j2], acc[i2][j2]);
    }

    // write C
#pragma unroll
    for (int i = 0; i < 8; i++) {
        size_t base = (size_t)(row0 + ty * 8 + i) * GG + col0 + tx * 8;
        *(float4*)(g_w + base)     = make_float4(acc[i][0], acc[i][1], acc[i][2], acc[i][3]);
        *(float4*)(g_w + base + 4) = make_float4(acc[i][4], acc[i][5], acc[i][6], acc[i][7]);
    }
}

// ---------------- batch-norm stats (deterministic two-stage) ----------------
__global__ void stats_partial_kernel()
{
    int col = blockIdx.x * 256 + threadIdx.x;   // grid.x = 8
    int r0  = blockIdx.y * 128;                 // grid.y = 125
    float s = 0.f, q = 0.f;
    for (int i = 0; i < 128; i++) {
        float v = g_w[(size_t)(r0 + i) * GG + col];
        s += v;
        q += v * v;
    }
    g_psum[blockIdx.y * GG + col] = s;
    g_psq [blockIdx.y * GG + col] = q;
}

__global__ void stats_final_kernel(const float* __restrict__ gamma,
                                   const float* __restrict__ beta)
{
    int col = blockIdx.x * 256 + threadIdx.x;   // grid.x = 8
    float s = 0.f, q = 0.f;
    for (int i = 0; i < 125; i++) {
        s += g_psum[i * GG + col];
        q += g_psq [i * GG + col];
    }
    float mean = s * (1.f / 16000.f);
    float var  = q * (1.f / 16000.f) - mean * mean;
    float sc   = gamma[col] * rsqrtf(var + 1e-5f);
    g_scale[col] = sc;
    g_shift[col] = beta[col] - mean * sc;
}

// ---------------- normalize + transpose: g_wT[t][g][b2] = g_w[b2,t][g]*sc+sh ----
__global__ __launch_bounds__(256) void normT_kernel()
{
    __shared__ float tile[32][33];
    int g0  = blockIdx.x * 32;
    int t   = blockIdx.y;
    int tid = threadIdx.x;
    {
        int b2 = tid >> 3, gq = (tid & 7) * 4;
        float4 v = *(const float4*)(g_w + (size_t)(b2 * TT + t) * GG + g0 + gq);
        tile[b2][gq + 0] = v.x; tile[b2][gq + 1] = v.y;
        tile[b2][gq + 2] = v.z; tile[b2][gq + 3] = v.w;
    }
    __syncthreads();
    {
        int gr = tid >> 3, bq = (tid & 7) * 4;
        float sc = g_scale[g0 + gr], sh = g_shift[g0 + gr];
        float4 o;
        o.x = tile[bq + 0][gr] * sc + sh;
        o.y = tile[bq + 1][gr] * sc + sh;
        o.z = tile[bq + 2][gr] * sc + sh;
        o.w = tile[bq + 3][gr] * sc + sh;
        *(float4*)(g_wT + ((size_t)t * GG + g0 + gr) * B2 + bq) = o;
    }
}

__global__ void reset_bar_kernel() { g_bar = 0u; }

// ---------------- persistent recurrence ----------------
// 128 blocks (1/SM), 256 threads. Block owns h-cols [blk*8, +8).
// Warp pair (p, p+4): p handles cols {blk*8+2p, +1}; the two warps of a pair
// split k into interleaved quads (s=0: quads 0,2,4,..; s=1: 1,3,5,..) and
// combine partial sums through smem once per step. h staged by cp.async in
// 4 pipelined chunks. w reads come pre-normalized & transposed from g_wT.
#define REC_SMEM ((16 * 1024 + HS + 256 + 512) * 4)

__device__ __forceinline__ void cp16(unsigned int d, const void* s) {
    asm volatile("cp.async.cg.shared.global [%0], [%1], 16;" :: "r"(d), "l"(s));
}

__device__ __forceinline__ void grid_barrier(unsigned int phase)
{
    __syncthreads();
    if (threadIdx.x == 0) {
        __threadfence();
        atomicAdd(&g_bar, 1u);
        unsigned int target = phase * gridDim.x;
        while (*((volatile unsigned int*)&g_bar) < target) { }
        __threadfence();
    }
    __syncthreads();
}

__global__ __launch_bounds__(256, 1) void recur_kernel(const float* __restrict__ U,
                                                       float* __restrict__ out,
                                                       int layer)
{
    extern __shared__ float sm[];
    float* Us = sm;                   // 16*1024 : U slice rows (8 a-rows, 8 z-rows)
    float* Hs = sm + 16 * 1024;       // 32768   : staged h, [k][b]
    float* So = Hs + HS;              // 256     : out staging [b][8 cols]
    float* Pa = So + 256;             // 512     : partial-sum exchange

    const int tid  = threadIdx.x;
    const int blk  = blockIdx.x;
    const int w    = tid >> 5;
    const int lane = tid & 31;
    const int p    = w & 3;           // column pair 0..3
    const int s    = w >> 2;          // k-half 0/1
    const int ga0  = blk * 8 + 2 * p;
    const int ga1  = ga0 + 1;

    // load U slice into SMEM: rows 0..7 = a-rows, 8..15 = z-rows
    for (int e = tid; e < 16 * 256; e += 256) {
        int rr = e >> 8, c4 = e & 255;
        int grow = (rr < 8) ? (blk * 8 + rr) : (HH + blk * 8 + (rr - 8));
        ((float4*)Us)[rr * 256 + c4] = ((const float4*)U)[(size_t)grow * 256 + c4];
    }

    // zero h parity 0 (128*256 = HS exactly)
    g_h[blk * 256 + tid] = 0.f;

    grid_barrier(1);

    const float* U0 = Us + (2 * p) * 1024;          // a, col0
    const float* U1 = Us + (2 * p + 1) * 1024;      // a, col1
    const float* U2 = Us + (8 + 2 * p) * 1024;      // z, col0
    const float* U3 = Us + (8 + 2 * p + 1) * 1024;  // z, col1

    unsigned int hs_u32 = (unsigned int)__cvta_generic_to_shared(Hs);
    float hp0 = 0.f, hp1 = 0.f;

    for (int t = 0; t < TT; t++) {
        const int cur = t & 1;
        const int nxt = cur ^ 1;

        float a0 = 0.f, a1 = 0.f, a2 = 0.f, a3 = 0.f;
        if (s == 0) {
            const float* wt = g_wT + (size_t)t * GG * B2;
            a0 = wt[ga0 * 32 + lane];
            a1 = wt[ga1 * 32 + lane];
            a2 = wt[(HH + ga0) * 32 + lane];
            a3 = wt[(HH + ga1) * 32 + lane];
        }

        // issue 4 async chunks of h staging (2048 float4 each)
        const float* hsrc = g_h + cur * HS;
#pragma unroll
        for (int c = 0; c < 4; c++) {
#pragma unroll
            for (int j = 0; j < 8; j++) {
                int e4 = c * 2048 + j * 256 + tid;
                cp16(hs_u32 + e4 * 16, hsrc + e4 * 4);
            }
            asm volatile("cp.async.commit_group;");
        }

        // pipelined compute over chunks
#pragma unroll
        for (int c = 0; c < 4; c++) {
            if      (c == 0) asm volatile("cp.async.wait_group 3;");
            else if (c == 1) asm volatile("cp.async.wait_group 2;");
            else if (c == 2) asm volatile("cp.async.wait_group 1;");
            else             asm volatile("cp.async.wait_group 0;");
            __syncthreads();

            const int kend = c * 256 + 256;
#pragma unroll 4
            for (int k = c * 256 + s * 4; k < kend; k += 8) {
                float4 u0 = *(const float4*)(U0 + k);
                float4 u1 = *(const float4*)(U1 + k);
                float4 u2 = *(const float4*)(U2 + k);
                float4 u3 = *(const float4*)(U3 + k);
                float h0 = Hs[(k + 0) * 32 + lane];
                float h1 = Hs[(k + 1) * 32 + lane];
                float h2 = Hs[(k + 2) * 32 + lane];
                float h3 = Hs[(k + 3) * 32 + lane];
                a0 = fmaf(u0.x, h0, a0); a0 = fmaf(u0.y, h1, a0);
                a0 = fmaf(u0.z, h2, a0); a0 = fmaf(u0.w, h3, a0);
                a1 = fmaf(u1.x, h0, a1); a1 = fmaf(u1.y, h1, a1);
                a1 = fmaf(u1.z, h2, a1); a1 = fmaf(u1.w, h3, a1);
                a2 = fmaf(u2.x, h0, a2); a2 = fmaf(u2.y, h1, a2);
                a2 = fmaf(u2.z, h2, a2); a2 = fmaf(u2.w, h3, a2);
                a3 = fmaf(u3.x, h0, a3); a3 = fmaf(u3.y, h1, a3);
                a3 = fmaf(u3.z, h2, a3); a3 = fmaf(u3.w, h3, a3);
            }
        }

        // combine k-halves
        if (s == 1) {
            Pa[0 * 128 + p * 32 + lane] = a0;
            Pa[1 * 128 + p * 32 + lane] = a1;
            Pa[2 * 128 + p * 32 + lane] = a2;
            Pa[3 * 128 + p * 32 + lane] = a3;
        }
        __syncthreads();
        if (s == 0) {
            a0 += Pa[0 * 128 + p * 32 + lane];
            a1 += Pa[1 * 128 + p * 32 + lane];
            a2 += Pa[2 * 128 + p * 32 + lane];
            a3 += Pa[3 * 128 + p * 32 + lane];
            float z0  = 1.f / (1.f + expf(-a2));
            float z1  = 1.f / (1.f + expf(-a3));
            float hn0 = z0 * hp0 + (1.f - z0) * fmaxf(a0, 0.f);
            float hn1 = z1 * hp1 + (1.f - z1) * fmaxf(a1, 0.f);
            hp0 = hn0; hp1 = hn1;
            g_h[nxt * HS + ga0 * 32 + lane] = hn0;
            g_h[nxt * HS + ga1 * 32 + lane] = hn1;
            So[lane * 8 + 2 * p]     = hn0;
            So[lane * 8 + 2 * p + 1] = hn1;
        }
        __syncthreads();

        // coalesced sequence-output write (8 consecutive k per batch row)
        {
            int b = tid >> 3, kk = tid & 7;
            float v = So[b * 8 + kk];
            if (layer == 0) {
                g_hs0[(size_t)(b * TT + t) * HH + blk * 8 + kk] = v;
            } else {
                if (b < BB)
                    out[(size_t)(b * TT + t) * GG + blk * 8 + kk] = v;
                else
                    out[(size_t)((b - BB) * TT + (TT - 1 - t)) * GG + HH + blk * 8 + kk] = v;
            }
        }

        grid_barrier((unsigned int)t + 2u);
    }
}

// ---------------- launch ----------------
extern "C" void kernel_launch(void* const* d_in, const int* in_sizes, int n_in,
                              void* d_out, int out_size)
{
    const float* x  = (const float*)d_in[0];
    const float* w0 = (const float*)d_in[1];
    const float* u0 = (const float*)d_in[2];
    const float* g0 = (const float*)d_in[3];
    const float* b0 = (const float*)d_in[4];
    const float* w1 = (const float*)d_in[5];
    const float* u1 = (const float*)d_in[6];
    const float* g1 = (const float*)d_in[7];
    const float* b1 = (const float*)d_in[8];
    float* out = (float*)d_out;

    cudaFuncSetAttribute(recur_kernel, cudaFuncAttributeMaxDynamicSharedMemorySize, REC_SMEM);

    dim3 ggrid(GG / 128, NROWS / 128);   // (16, 125)
    dim3 sgrid(GG / 256, 125);           // (8, 125)
    dim3 tgrid(GG / 32, TT);             // (64, 500)

    // ---- layer 0 ----
    gemm_kernel<<<ggrid, 256>>>(x, w0, 512, 0);
    stats_partial_kernel<<<sgrid, 256>>>();
    stats_final_kernel<<<GG / 256, 256>>>(g0, b0);
    normT_kernel<<<tgrid, 256>>>();
    reset_bar_kernel<<<1, 1>>>();
    recur_kernel<<<128, 256, REC_SMEM>>>(u0, out, 0);

    // ---- layer 1 ----
    gemm_kernel<<<ggrid, 256>>>(x, w1, 2048, 1);
    stats_partial_kernel<<<sgrid, 256>>>();
    stats_final_kernel<<<GG / 256, 256>>>(g1, b1);
    normT_kernel<<<tgrid, 256>>>();
    reset_bar_kernel<<<1, 1>>>();
    recur_kernel<<<128, 256, REC_SMEM>>>(u1, out, 1);
}

// round 9
// speedup vs baseline: 1.5747x; 1.1245x over previous
#include <cuda_runtime.h>
#include <math.h>
#include <stdint.h>

// Problem constants
#define BB    16
#define B2    32
#define TT    500
#define HH    1024
#define GG    2048
#define NROWS 16000
#define HS    (HH * B2)

// ---------------- scratch (device globals; no allocation) ----------------
__device__ __align__(128) float g_w  [(size_t)NROWS * GG];   // raw input projections [r][g]
__device__ __align__(128) float g_wT [(size_t)TT * GG * B2]; // normalized, [t][g][b2]
__device__ __align__(128) float g_hs0[(size_t)B2 * TT * HH]; // layer-0 hidden sequence
__device__ __align__(128) float g_h  [2 * HS];               // double-buffered h, [parity][k][b]
__device__ __align__(128) float g_psum[125 * GG];
__device__ __align__(128) float g_psq [125 * GG];
__device__ float g_scale[GG];
__device__ float g_shift[GG];
__device__ unsigned int g_bar;
// tf32 hi/lo planes for 3xTF32 GEMM
__device__ __align__(128) unsigned g_Ah[(size_t)NROWS * GG];
__device__ __align__(128) unsigned g_Al[(size_t)NROWS * GG];
__device__ __align__(128) unsigned g_Wh[(size_t)GG * GG];
__device__ __align__(128) unsigned g_Wl[(size_t)GG * GG];

// ---------------- helpers ----------------
__device__ __forceinline__ void tf32split(float v, unsigned& hi, unsigned& lo)
{
    asm("cvt.rna.tf32.f32 %0, %1;" : "=r"(hi) : "f"(v));
    float l = v - __uint_as_float(hi);
    asm("cvt.rna.tf32.f32 %0, %1;" : "=r"(lo) : "f"(l));
}

__device__ __forceinline__ void cp16(unsigned int d, const void* s) {
    asm volatile("cp.async.cg.shared.global [%0], [%1], 16;" :: "r"(d), "l"(s));
}

__device__ __forceinline__ void mma_tf32(float* c, const unsigned* a, const unsigned* b)
{
    asm volatile(
        "mma.sync.aligned.m16n8k8.row.col.f32.tf32.tf32.f32 "
        "{%0,%1,%2,%3}, {%4,%5,%6,%7}, {%8,%9}, {%0,%1,%2,%3};"
        : "+f"(c[0]), "+f"(c[1]), "+f"(c[2]), "+f"(c[3])
        : "r"(a[0]), "r"(a[1]), "r"(a[2]), "r"(a[3]), "r"(b[0]), "r"(b[1]));
}

// ---------------- prep: gather A (bidir concat) + tf32 split ----------------
__global__ __launch_bounds__(256) void convA_kernel(const float* __restrict__ X,
                                                    int F, int layer)
{
    int r  = blockIdx.x;
    int b2 = r / TT;
    int t  = r - b2 * TT;
    int b  = b2 & 15;
    int tt = (b2 < BB) ? t : (TT - 1 - t);
    const float* srcF;
    const float* srcB;
    if (layer == 0) {
        srcF = X + (size_t)(b * TT + tt) * 512;
        srcB = srcF;
    } else {
        srcF = g_hs0 + (size_t)(b * TT + tt) * HH;
        srcB = g_hs0 + (size_t)((b + 16) * TT + (TT - 1 - tt)) * HH - HH; // valid for f>=HH
    }
    size_t base = (size_t)r * F;
    for (int f = threadIdx.x; f < F; f += 256) {
        float v = (layer == 0 || f < HH) ? srcF[f] : srcB[f];
        unsigned hi, lo;
        tf32split(v, hi, lo);
        g_Ah[base + f] = hi;
        g_Al[base + f] = lo;
    }
}

__global__ __launch_bounds__(256) void convW_kernel(const float* __restrict__ Wm, int n)
{
    int i = (blockIdx.x * 256 + threadIdx.x) * 4;
    if (i >= n) return;
    float4 v = *(const float4*)(Wm + i);
    unsigned h0, l0, h1, l1, h2, l2, h3, l3;
    tf32split(v.x, h0, l0);
    tf32split(v.y, h1, l1);
    tf32split(v.z, h2, l2);
    tf32split(v.w, h3, l3);
    *(uint4*)(g_Wh + i) = make_uint4(h0, h1, h2, h3);
    *(uint4*)(g_Wl + i) = make_uint4(l0, l1, l2, l3);
}

// ---------------- 3xTF32 GEMM: g_w[r][g] = sum_f A(r,f)*W[g][f] ----------------
// Block tile 128x128, k-tile 16, cp.async double buffer.
// Smem planes: [buf][Ah,Al,Bh,Bl][128 rows x stride 20] (rows hold 16 k-values).
// Warp layout 2x4: warp tile 64x32 = 4 m16 x 4 n8 mma tiles; 3 MMAs per tile per k8.
#define PLANE 2560                    // 128*20 u32
#define GEMM_SMEM (2 * 4 * PLANE * 4) // 81920 bytes

__global__ __launch_bounds__(256, 1) void gemm_tf32_kernel(int F)
{
    extern __shared__ unsigned smu[];

    const int tid  = threadIdx.x;
    const int row0 = blockIdx.y * 128;
    const int col0 = blockIdx.x * 128;
    const int w    = tid >> 5;
    const int lane = tid & 31;
    const int grp  = lane >> 2;
    const int tg   = lane & 3;
    const int wm   = w >> 2;   // 0..1
    const int wn   = w & 3;    // 0..3

    const unsigned smbase = (unsigned)__cvta_generic_to_shared(smu);

    // per-thread load assignment: 2 chunks per plane, 4 planes
    const int lrow = tid >> 1;           // 0..127 (with rep covering 2nd half)
    // tasks: idx = rep*256+tid -> row=idx>>2, ch=idx&3
    const int nt = F / 16;

    float c[4][4][4];
#pragma unroll
    for (int i = 0; i < 4; i++)
#pragma unroll
        for (int j = 0; j < 4; j++)
#pragma unroll
            for (int q = 0; q < 4; q++) c[i][j][q] = 0.f;

    (void)lrow;

#define LOAD_TILE(IT, BUF)                                                           \
    do {                                                                             \
        int kk = (IT) * 16;                                                          \
        unsigned sb = smbase + (BUF) * 4 * PLANE * 4;                                \
        _Pragma("unroll")                                                            \
        for (int p = 0; p < 4; p++) {                                                \
            const unsigned* src = (p == 0) ? g_Ah : (p == 1) ? g_Al                  \
                                  : (p == 2) ? g_Wh : g_Wl;                          \
            size_t gb = (p < 2) ? ((size_t)row0 * F) : ((size_t)col0 * F);           \
            _Pragma("unroll")                                                        \
            for (int rep = 0; rep < 2; rep++) {                                      \
                int idx = rep * 256 + tid;                                           \
                int row = idx >> 2, ch = idx & 3;                                    \
                cp16(sb + p * PLANE * 4 + row * 80 + ch * 16,                        \
                     src + gb + (size_t)row * F + kk + ch * 4);                      \
            }                                                                        \
        }                                                                            \
        asm volatile("cp.async.commit_group;");                                      \
    } while (0)

    LOAD_TILE(0, 0);

    for (int it = 0; it < nt; it++) {
        if (it + 1 < nt) {
            LOAD_TILE(it + 1, (it + 1) & 1);
            asm volatile("cp.async.wait_group 1;");
        } else {
            asm volatile("cp.async.wait_group 0;");
        }
        __syncthreads();

        const unsigned* SA  = smu + (it & 1) * 4 * PLANE;
        const unsigned* SAl = SA + PLANE;
        const unsigned* SBh = SA + 2 * PLANE;
        const unsigned* SBl = SA + 3 * PLANE;

#pragma unroll
        for (int k0 = 0; k0 < 16; k0 += 8) {
            unsigned ah[4][4], al[4][4], bh[4][2], bl[4][2];
#pragma unroll
            for (int mi = 0; mi < 4; mi++) {
                int m = wm * 64 + mi * 16;
                ah[mi][0] = SA [(m + grp)     * 20 + k0 + tg];
                ah[mi][1] = SA [(m + 8 + grp) * 20 + k0 + tg];
                ah[mi][2] = SA [(m + grp)     * 20 + k0 + tg + 4];
                ah[mi][3] = SA [(m + 8 + grp) * 20 + k0 + tg + 4];
                al[mi][0] = SAl[(m + grp)     * 20 + k0 + tg];
                al[mi][1] = SAl[(m + 8 + grp) * 20 + k0 + tg];
                al[mi][2] = SAl[(m + grp)     * 20 + k0 + tg + 4];
                al[mi][3] = SAl[(m + 8 + grp) * 20 + k0 + tg + 4];
            }
#pragma unroll
            for (int ni = 0; ni < 4; ni++) {
                int n = wn * 32 + ni * 8;
                bh[ni][0] = SBh[(n + grp) * 20 + k0 + tg];
                bh[ni][1] = SBh[(n + grp) * 20 + k0 + tg + 4];
                bl[ni][0] = SBl[(n + grp) * 20 + k0 + tg];
                bl[ni][1] = SBl[(n + grp) * 20 + k0 + tg + 4];
            }
#pragma unroll
            for (int mi = 0; mi < 4; mi++)
#pragma unroll
                for (int ni = 0; ni < 4; ni++) {
                    mma_tf32(c[mi][ni], ah[mi], bh[ni]);  // hi*hi
                    mma_tf32(c[mi][ni], ah[mi], bl[ni]);  // hi*lo
                    mma_tf32(c[mi][ni], al[mi], bh[ni]);  // lo*hi
                }
        }
        __syncthreads();
    }

    // epilogue
#pragma unroll
    for (int mi = 0; mi < 4; mi++)
#pragma unroll
        for (int ni = 0; ni < 4; ni++) {
            int r   = row0 + wm * 64 + mi * 16 + grp;
            int cix = col0 + wn * 32 + ni * 8 + tg * 2;
            *(float2*)(g_w + (size_t)r * GG + cix)       = make_float2(c[mi][ni][0], c[mi][ni][1]);
            *(float2*)(g_w + (size_t)(r + 8) * GG + cix) = make_float2(c[mi][ni][2], c[mi][ni][3]);
        }
#undef LOAD_TILE
}

// ---------------- batch-norm stats (deterministic two-stage) ----------------
__global__ void stats_partial_kernel()
{
    int col = blockIdx.x * 256 + threadIdx.x;
    int r0  = blockIdx.y * 128;
    float s = 0.f, q = 0.f;
    for (int i = 0; i < 128; i++) {
        float v = g_w[(size_t)(r0 + i) * GG + col];
        s += v;
        q += v * v;
    }
    g_psum[blockIdx.y * GG + col] = s;
    g_psq [blockIdx.y * GG + col] = q;
}

__global__ void stats_final_kernel(const float* __restrict__ gamma,
                                   const float* __restrict__ beta)
{
    int col = blockIdx.x * 256 + threadIdx.x;
    float s = 0.f, q = 0.f;
    for (int i = 0; i < 125; i++) {
        s += g_psum[i * GG + col];
        q += g_psq [i * GG + col];
    }
    float mean = s * (1.f / 16000.f);
    float var  = q * (1.f / 16000.f) - mean * mean;
    float sc   = gamma[col] * rsqrtf(var + 1e-5f);
    g_scale[col] = sc;
    g_shift[col] = beta[col] - mean * sc;
}

// ---------------- normalize + transpose: g_wT[t][g][b2] ----------------
__global__ __launch_bounds__(256) void normT_kernel()
{
    __shared__ float tile[32][33];
    int g0  = blockIdx.x * 32;
    int t   = blockIdx.y;
    int tid = threadIdx.x;
    {
        int b2 = tid >> 3, gq = (tid & 7) * 4;
        float4 v = *(const float4*)(g_w + (size_t)(b2 * TT + t) * GG + g0 + gq);
        tile[b2][gq + 0] = v.x; tile[b2][gq + 1] = v.y;
        tile[b2][gq + 2] = v.z; tile[b2][gq + 3] = v.w;
    }
    __syncthreads();
    {
        int gr = tid >> 3, bq = (tid & 7) * 4;
        float sc = g_scale[g0 + gr], sh = g_shift[g0 + gr];
        float4 o;
        o.x = tile[bq + 0][gr] * sc + sh;
        o.y = tile[bq + 1][gr] * sc + sh;
        o.z = tile[bq + 2][gr] * sc + sh;
        o.w = tile[bq + 3][gr] * sc + sh;
        *(float4*)(g_wT + ((size_t)t * GG + g0 + gr) * B2 + bq) = o;
    }
}

__global__ void reset_bar_kernel() { g_bar = 0u; }

// ---------------- persistent recurrence (unchanged from round 7) ----------------
#define REC_SMEM ((16 * 1024 + HS + 256 + 512) * 4)

__device__ __forceinline__ void grid_barrier(unsigned int phase)
{
    __syncthreads();
    if (threadIdx.x == 0) {
        __threadfence();
        atomicAdd(&g_bar, 1u);
        unsigned int target = phase * gridDim.x;
        while (*((volatile unsigned int*)&g_bar) < target) { }
        __threadfence();
    }
    __syncthreads();
}

__global__ __launch_bounds__(256, 1) void recur_kernel(const float* __restrict__ U,
                                                       float* __restrict__ out,
                                                       int layer)
{
    extern __shared__ float sm[];
    float* Us = sm;                   // 16*1024
    float* Hs = sm + 16 * 1024;       // 32768 [k][b]
    float* So = Hs + HS;              // 256
    float* Pa = So + 256;             // 512

    const int tid  = threadIdx.x;
    const int blk  = blockIdx.x;
    const int w    = tid >> 5;
    const int lane = tid & 31;
    const int p    = w & 3;
    const int s    = w >> 2;
    const int ga0  = blk * 8 + 2 * p;
    const int ga1  = ga0 + 1;

    for (int e = tid; e < 16 * 256; e += 256) {
        int rr = e >> 8, c4 = e & 255;
        int grow = (rr < 8) ? (blk * 8 + rr) : (HH + blk * 8 + (rr - 8));
        ((float4*)Us)[rr * 256 + c4] = ((const float4*)U)[(size_t)grow * 256 + c4];
    }

    g_h[blk * 256 + tid] = 0.f;

    grid_barrier(1);

    const float* U0 = Us + (2 * p) * 1024;
    const float* U1 = Us + (2 * p + 1) * 1024;
    const float* U2 = Us + (8 + 2 * p) * 1024;
    const float* U3 = Us + (8 + 2 * p + 1) * 1024;

    unsigned int hs_u32 = (unsigned int)__cvta_generic_to_shared(Hs);
    float hp0 = 0.f, hp1 = 0.f;

    for (int t = 0; t < TT; t++) {
        const int cur = t & 1;
        const int nxt = cur ^ 1;

        float a0 = 0.f, a1 = 0.f, a2 = 0.f, a3 = 0.f;
        if (s == 0) {
            const float* wt = g_wT + (size_t)t * GG * B2;
            a0 = wt[ga0 * 32 + lane];
            a1 = wt[ga1 * 32 + lane];
            a2 = wt[(HH + ga0) * 32 + lane];
            a3 = wt[(HH + ga1) * 32 + lane];
        }

        const float* hsrc = g_h + cur * HS;
#pragma unroll
        for (int c2 = 0; c2 < 4; c2++) {
#pragma unroll
            for (int j = 0; j < 8; j++) {
                int e4 = c2 * 2048 + j * 256 + tid;
                cp16(hs_u32 + e4 * 16, hsrc + e4 * 4);
            }
            asm volatile("cp.async.commit_group;");
        }

#pragma unroll
        for (int c2 = 0; c2 < 4; c2++) {
            if      (c2 == 0) asm volatile("cp.async.wait_group 3;");
            else if (c2 == 1) asm volatile("cp.async.wait_group 2;");
            else if (c2 == 2) asm volatile("cp.async.wait_group 1;");
            else              asm volatile("cp.async.wait_group 0;");
            __syncthreads();

            const int kend = c2 * 256 + 256;
#pragma unroll 4
            for (int k = c2 * 256 + s * 4; k < kend; k += 8) {
                float4 u0 = *(const float4*)(U0 + k);
                float4 u1 = *(const float4*)(U1 + k);
                float4 u2 = *(const float4*)(U2 + k);
                float4 u3 = *(const float4*)(U3 + k);
                float h0 = Hs[(k + 0) * 32 + lane];
                float h1 = Hs[(k + 1) * 32 + lane];
                float h2 = Hs[(k + 2) * 32 + lane];
                float h3 = Hs[(k + 3) * 32 + lane];
                a0 = fmaf(u0.x, h0, a0); a0 = fmaf(u0.y, h1, a0);
                a0 = fmaf(u0.z, h2, a0); a0 = fmaf(u0.w, h3, a0);
                a1 = fmaf(u1.x, h0, a1); a1 = fmaf(u1.y, h1, a1);
                a1 = fmaf(u1.z, h2, a1); a1 = fmaf(u1.w, h3, a1);
                a2 = fmaf(u2.x, h0, a2); a2 = fmaf(u2.y, h1, a2);
                a2 = fmaf(u2.z, h2, a2); a2 = fmaf(u2.w, h3, a2);
                a3 = fmaf(u3.x, h0, a3); a3 = fmaf(u3.y, h1, a3);
                a3 = fmaf(u3.z, h2, a3); a3 = fmaf(u3.w, h3, a3);
            }
        }

        if (s == 1) {
            Pa[0 * 128 + p * 32 + lane] = a0;
            Pa[1 * 128 + p * 32 + lane] = a1;
            Pa[2 * 128 + p * 32 + lane] = a2;
            Pa[3 * 128 + p * 32 + lane] = a3;
        }
        __syncthreads();
        if (s == 0) {
            a0 += Pa[0 * 128 + p * 32 + lane];
            a1 += Pa[1 * 128 + p * 32 + lane];
            a2 += Pa[2 * 128 + p * 32 + lane];
            a3 += Pa[3 * 128 + p * 32 + lane];
            float z0  = 1.f / (1.f + expf(-a2));
            float z1  = 1.f / (1.f + expf(-a3));
            float hn0 = z0 * hp0 + (1.f - z0) * fmaxf(a0, 0.f);
            float hn1 = z1 * hp1 + (1.f - z1) * fmaxf(a1, 0.f);
            hp0 = hn0; hp1 = hn1;
            g_h[nxt * HS + ga0 * 32 + lane] = hn0;
            g_h[nxt * HS + ga1 * 32 + lane] = hn1;
            So[lane * 8 + 2 * p]     = hn0;
            So[lane * 8 + 2 * p + 1] = hn1;
        }
        __syncthreads();

        {
            int b = tid >> 3, kk = tid & 7;
            float v = So[b * 8 + kk];
            if (layer == 0) {
                g_hs0[(size_t)(b * TT + t) * HH + blk * 8 + kk] = v;
            } else {
                if (b < BB)
                    out[(size_t)(b * TT + t) * GG + blk * 8 + kk] = v;
                else
                    out[(size_t)((b - BB) * TT + (TT - 1 - t)) * GG + HH + blk * 8 + kk] = v;
            }
        }

        grid_barrier((unsigned int)t + 2u);
    }
}

// ---------------- launch ----------------
extern "C" void kernel_launch(void* const* d_in, const int* in_sizes, int n_in,
                              void* d_out, int out_size)
{
    const float* x  = (const float*)d_in[0];
    const float* w0 = (const float*)d_in[1];
    const float* u0 = (const float*)d_in[2];
    const float* g0 = (const float*)d_in[3];
    const float* b0 = (const float*)d_in[4];
    const float* w1 = (const float*)d_in[5];
    const float* u1 = (const float*)d_in[6];
    const float* g1 = (const float*)d_in[7];
    const float* b1 = (const float*)d_in[8];
    float* out = (float*)d_out;

    cudaFuncSetAttribute(recur_kernel, cudaFuncAttributeMaxDynamicSharedMemorySize, REC_SMEM);
    cudaFuncSetAttribute(gemm_tf32_kernel, cudaFuncAttributeMaxDynamicSharedMemorySize, GEMM_SMEM);

    dim3 ggrid(GG / 128, NROWS / 128);   // (16, 125)
    dim3 sgrid(GG / 256, 125);           // (8, 125)
    dim3 tgrid(GG / 32, TT);             // (64, 500)

    // ---- layer 0 ----
    convA_kernel<<<NROWS, 256>>>(x, 512, 0);
    convW_kernel<<<(GG * 512) / 1024, 256>>>(w0, GG * 512);
    gemm_tf32_kernel<<<ggrid, 256, GEMM_SMEM>>>(512);
    stats_partial_kernel<<<sgrid, 256>>>();
    stats_final_kernel<<<GG / 256, 256>>>(g0, b0);
    normT_kernel<<<tgrid, 256>>>();
    reset_bar_kernel<<<1, 1>>>();
    recur_kernel<<<128, 256, REC_SMEM>>>(u0, out, 0);

    // ---- layer 1 ----
    convA_kernel<<<NROWS, 256>>>(x, 2048, 1);
    convW_kernel<<<(GG * GG) / 1024, 256>>>(w1, GG * GG);
    gemm_tf32_kernel<<<ggrid, 256, GEMM_SMEM>>>(2048);
    stats_partial_kernel<<<sgrid, 256>>>();
    stats_final_kernel<<<GG / 256, 256>>>(g1, b1);
    normT_kernel<<<tgrid, 256>>>();
    reset_bar_kernel<<<1, 1>>>();
    recur_kernel<<<128, 256, REC_SMEM>>>(u1, out, 1);
}